// round 10
// baseline (speedup 1.0000x reference)
#include <cuda_runtime.h>
#include <math.h>
#include <stdint.h>
#include <mma.h>

using namespace nvcuda;

// ---------------------------------------------------------------------------
// Problem constants: B=2, T=2048, D=1024, NH=16, DH=64, MLP=4096. M = 4096.
// ---------------------------------------------------------------------------
#define M_ROWS 4096
#define D_DIM  1024
#define D3     3072
#define MLP_D  4096

// Scratch (device globals; no allocation allowed)
__device__ float g_xn  [M_ROWS * D_DIM];
__device__ float g_qkv [M_ROWS * D3];
__device__ float g_att [M_ROWS * D_DIM];
__device__ float g_x   [M_ROWS * D_DIM];
__device__ float g_hn  [M_ROWS * D_DIM];
__device__ float g_h   [M_ROWS * MLP_D];
// tf32-pre-rounded weights
__device__ float g_wqkv_r[D_DIM * D3];
__device__ float g_wout_r[D_DIM * D_DIM];
__device__ float g_w1_r  [D_DIM * MLP_D];
__device__ float g_w2_r  [MLP_D * D_DIM];

__device__ __forceinline__ float to_tf32(float x) {
    float y;
    asm("cvt.rna.tf32.f32 %0, %1;" : "=f"(y) : "f"(x));
    return y;
}

// cp.async helpers
__device__ __forceinline__ void cp16(uint32_t dst, const void* src) {
    asm volatile("cp.async.cg.shared.global [%0], [%1], 16;" :: "r"(dst), "l"(src));
}
#define CP_COMMIT() asm volatile("cp.async.commit_group;" ::: "memory")
template <int N>
__device__ __forceinline__ void cp_wait() {
    asm volatile("cp.async.wait_group %0;" :: "n"(N) : "memory");
}

// ---------------------------------------------------------------------------
// Elementwise tf32 rounding (for weights). n % 1024 == 0.
// ---------------------------------------------------------------------------
__global__ void round_tf32_k(const float* __restrict__ in, float* __restrict__ out) {
    const int i = (blockIdx.x * 256 + threadIdx.x) * 4;
    float4 v = *(const float4*)(in + i);
    v.x = to_tf32(v.x); v.y = to_tf32(v.y); v.z = to_tf32(v.z); v.w = to_tf32(v.w);
    *(float4*)(out + i) = v;
}

// ---------------------------------------------------------------------------
// LayerNorm: one block (256 threads) per row of 1024 floats.
// ROUND: round output to tf32 (output feeds only GEMM A-operands).
// ---------------------------------------------------------------------------
template <int ROUND>
__global__ void ln_k(const float* __restrict__ x, const float* __restrict__ g,
                     const float* __restrict__ b, float* __restrict__ y) {
    __shared__ float rs[8], rss[8], sh[2];
    const int row = blockIdx.x;
    const int tid = threadIdx.x;
    const float4 v = *(const float4*)(x + (size_t)row * 1024 + tid * 4);
    float s  = v.x + v.y + v.z + v.w;
    float ss = v.x * v.x + v.y * v.y + v.z * v.z + v.w * v.w;
#pragma unroll
    for (int off = 16; off >= 1; off >>= 1) {
        s  += __shfl_xor_sync(0xffffffffu, s, off);
        ss += __shfl_xor_sync(0xffffffffu, ss, off);
    }
    if ((tid & 31) == 0) { rs[tid >> 5] = s; rss[tid >> 5] = ss; }
    __syncthreads();
    if (tid == 0) {
        float S = 0.f, SS = 0.f;
#pragma unroll
        for (int w = 0; w < 8; w++) { S += rs[w]; SS += rss[w]; }
        sh[0] = S * (1.0f / 1024.0f);
        sh[1] = SS * (1.0f / 1024.0f);
    }
    __syncthreads();
    const float mu   = sh[0];
    const float var  = sh[1] - mu * mu;
    const float rstd = rsqrtf(var + 1e-5f);
    const float4 gg = *(const float4*)(g + tid * 4);
    const float4 bb = *(const float4*)(b + tid * 4);
    float4 o;
    o.x = (v.x - mu) * rstd * gg.x + bb.x;
    o.y = (v.y - mu) * rstd * gg.y + bb.y;
    o.z = (v.z - mu) * rstd * gg.z + bb.z;
    o.w = (v.w - mu) * rstd * gg.w + bb.w;
    if (ROUND) {
        o.x = to_tf32(o.x); o.y = to_tf32(o.y); o.z = to_tf32(o.z); o.w = to_tf32(o.w);
    }
    *(float4*)(y + (size_t)row * 1024 + tid * 4) = o;
}

// ---------------------------------------------------------------------------
// WMMA tf32 GEMM, 3-stage cp.async ring, ONE syncthreads per K-iteration.
// C[M,N] = A[M,K] @ B[K,N] (+ epilogue). A, B tf32-pre-rounded.
//   EPI 0: none  1: round_tf32  2: +bias+res  3: round_tf32(gelu(.+bias))
// CTA tile 128x128, BK=32, 256 threads, 8 warps, warp tile 32x64.
// ---------------------------------------------------------------------------
#define G_AS_LD 36
#define G_BS_LD 132
#define G_STG_FLOATS (128 * G_AS_LD + 32 * G_BS_LD)   // 8832
#define G_EP_LD 68
#define G_SMEM (3 * G_STG_FLOATS * 4)                 // 105984 B (epi 17408 fl fits)

__device__ __forceinline__ void g_load_stage(
    const float* __restrict__ A, const float* __restrict__ B,
    int N, int K, int m0, int n0, int k0, float* As, float* Bs, int tid) {
#pragma unroll
    for (int v = 0; v < 4; v++) {
        const int id = v * 256 + tid;
        const int r  = id >> 3;
        const int c4 = (id & 7) * 4;
        cp16((uint32_t)__cvta_generic_to_shared(&As[r * G_AS_LD + c4]),
             A + (size_t)(m0 + r) * K + k0 + c4);
    }
#pragma unroll
    for (int v = 0; v < 4; v++) {
        const int id = v * 256 + tid;
        const int r  = id >> 5;
        const int c4 = (id & 31) * 4;
        cp16((uint32_t)__cvta_generic_to_shared(&Bs[r * G_BS_LD + c4]),
             B + (size_t)(k0 + r) * N + n0 + c4);
    }
}

template <int EPI>
__global__ __launch_bounds__(256, 2)
void gemm_wmma(const float* __restrict__ A, const float* __restrict__ B,
               const float* __restrict__ bias, const float* __restrict__ res,
               float* __restrict__ C, int M, int N, int K) {
    extern __shared__ float sm[];
    float* As[3] = {sm, sm + G_STG_FLOATS, sm + 2 * G_STG_FLOATS};
    float* Bs[3] = {sm + 128 * G_AS_LD,
                    sm + G_STG_FLOATS + 128 * G_AS_LD,
                    sm + 2 * G_STG_FLOATS + 128 * G_AS_LD};

    const int tid  = threadIdx.x;
    const int wid  = tid >> 5;
    const int lane = tid & 31;
    const int m0 = blockIdx.y * 128;
    const int n0 = blockIdx.x * 128;
    const int wm = (wid & 3) * 32;
    const int wn = (wid >> 2) * 64;

    wmma::fragment<wmma::accumulator, 16, 16, 8, float> acc[2][4];
#pragma unroll
    for (int i = 0; i < 2; i++)
#pragma unroll
        for (int j = 0; j < 4; j++)
            wmma::fill_fragment(acc[i][j], 0.0f);

    const int NK = K / 32;   // >= 32 for all calls
    g_load_stage(A, B, N, K, m0, n0, 0,  As[0], Bs[0], tid);
    CP_COMMIT();
    g_load_stage(A, B, N, K, m0, n0, 32, As[1], Bs[1], tid);
    CP_COMMIT();

    for (int kt = 0; kt < NK; kt++) {
        if (kt == NK - 1) cp_wait<0>(); else cp_wait<1>();
        __syncthreads();

        // prefetch stage kt+2 into ring slot (safe: last readers of that slot
        // finished in iteration kt-1, before the barrier above)
        if (kt + 2 < NK) {
            g_load_stage(A, B, N, K, m0, n0, (kt + 2) * 32,
                         As[(kt + 2) % 3], Bs[(kt + 2) % 3], tid);
            CP_COMMIT();
        }

        const float* as = As[kt % 3];
        const float* bs = Bs[kt % 3];
#pragma unroll
        for (int kk = 0; kk < 4; kk++) {
            wmma::fragment<wmma::matrix_a, 16, 16, 8, wmma::precision::tf32,
                           wmma::row_major> af[2];
            wmma::fragment<wmma::matrix_b, 16, 16, 8, wmma::precision::tf32,
                           wmma::row_major> bf[4];
#pragma unroll
            for (int i = 0; i < 2; i++)
                wmma::load_matrix_sync(af[i], &as[(wm + i * 16) * G_AS_LD + kk * 8],
                                       G_AS_LD);
#pragma unroll
            for (int j = 0; j < 4; j++)
                wmma::load_matrix_sync(bf[j], &bs[(kk * 8) * G_BS_LD + wn + j * 16],
                                       G_BS_LD);
#pragma unroll
            for (int i = 0; i < 2; i++)
#pragma unroll
                for (int j = 0; j < 4; j++)
                    wmma::mma_sync(acc[i][j], af[i], bf[j], acc[i][j]);
        }
    }
    __syncthreads();   // protect ring smem before epilogue reuse

    // Epilogue: warp-private smem patch, then coalesced global write.
    float* ep = sm + wid * (32 * G_EP_LD);
#pragma unroll
    for (int i = 0; i < 2; i++)
#pragma unroll
        for (int j = 0; j < 4; j++)
            wmma::store_matrix_sync(&ep[(i * 16) * G_EP_LD + j * 16], acc[i][j],
                                    G_EP_LD, wmma::mem_row_major);
    __syncwarp();

#pragma unroll 4
    for (int r = 0; r < 32; r++) {
        const int m = m0 + wm + r;
#pragma unroll
        for (int cc = 0; cc < 2; cc++) {
            const int c = lane + cc * 32;
            const int n = n0 + wn + c;
            float v = ep[r * G_EP_LD + c];
            if (EPI == 2 || EPI == 3) v += bias[n];
            if (EPI == 2) v += res[(size_t)m * N + n];
            if (EPI == 3) v = 0.5f * v * (1.0f + erff(v * 0.7071067811865476f));
            if (EPI == 1 || EPI == 3) v = to_tf32(v);
            C[(size_t)m * N + n] = v;
        }
    }
}

// ---------------------------------------------------------------------------
// Tensor-core flash attention, cp.async double-buffered K/V.
// Block: 256 threads (8 warps), 64 q-rows x one head x one batch.
// K/V of tile kt+1 prefetched during compute of tile kt. 3 syncs/iter.
// qkv must be tf32-rounded already (GEMM EPI=1); Q rounded after *0.125.
// ---------------------------------------------------------------------------
#define FT_LD 68
#define FT_T  (64 * FT_LD)
#define FT_SMEM ((7 * FT_T + 128) * 4)   // Q,K0,K1,V0,V1,S,O + m,l = 122368 B

__device__ __forceinline__ void fa_load_kv(const float* __restrict__ kvbase, int kt,
                                           float* K, float* V, int tid) {
    const float* kb = kvbase + (size_t)(kt * 64) * 3072;
#pragma unroll
    for (int v = 0; v < 4; v++) {
        const int id = v * 256 + tid;
        const int r  = id >> 4;
        const int c4 = (id & 15) * 4;
        cp16((uint32_t)__cvta_generic_to_shared(&K[r * FT_LD + c4]),
             kb + (size_t)r * 3072 + c4);
        cp16((uint32_t)__cvta_generic_to_shared(&V[r * FT_LD + c4]),
             kb + 1024 + (size_t)r * 3072 + c4);
    }
}

__global__ __launch_bounds__(256, 1)
void flash_attn_tc(const float* __restrict__ qkv, float* __restrict__ out) {
    extern __shared__ float sm[];
    float* Qs = sm;
    float* Ks[2] = {sm + FT_T, sm + 2 * FT_T};
    float* Vs[2] = {sm + 3 * FT_T, sm + 4 * FT_T};
    float* Ss = sm + 5 * FT_T;
    float* Os = sm + 6 * FT_T;
    float* m_s = sm + 7 * FT_T;
    float* l_s = m_s + 64;

    const int qt = blockIdx.x;
    const int h  = blockIdx.y;
    const int b  = blockIdx.z;
    const int tid  = threadIdx.x;
    const int wid  = tid >> 5;
    const int r0 = (wid & 3) * 16;
    const int c0 = (wid >> 2) * 32;
    const int t0 = qt * 64;

    const float* kvbase = qkv + ((size_t)(b * 2048)) * 3072 + 1024 + h * 64;

    // Prefetch K/V tile 0
    fa_load_kv(kvbase, 0, Ks[0], Vs[0], tid);
    CP_COMMIT();

    // Load Q (scaled by 1/8 — exact — then tf32-rounded); zero Os; init m,l.
    const float* qbase = qkv + ((size_t)(b * 2048 + t0)) * 3072 + h * 64;
#pragma unroll
    for (int v = 0; v < 4; v++) {
        const int id = v * 256 + tid;
        const int r  = id >> 4;
        const int c4 = (id & 15) * 4;
        float4 x = *(const float4*)(qbase + (size_t)r * 3072 + c4);
        x.x = to_tf32(x.x * 0.125f); x.y = to_tf32(x.y * 0.125f);
        x.z = to_tf32(x.z * 0.125f); x.w = to_tf32(x.w * 0.125f);
        *(float4*)&Qs[r * FT_LD + c4] = x;
        *(float4*)&Os[r * FT_LD + c4] = make_float4(0.f, 0.f, 0.f, 0.f);
    }
    if (tid < 64) { m_s[tid] = -INFINITY; l_s[tid] = 0.f; }

    for (int kt = 0; kt < 32; kt++) {
        const int cur = kt & 1;
        cp_wait<0>();        // K/V tile kt resident
        __syncthreads();     // [A] KV visible; P@V of kt-1 done everywhere

        // Prefetch tile kt+1 into the other buffer (its last readers finished
        // in iteration kt-1, before barrier [A])
        if (kt + 1 < 32) {
            fa_load_kv(kvbase, kt + 1, Ks[cur ^ 1], Vs[cur ^ 1], tid);
            CP_COMMIT();
        }

        // S = Q @ K^T  (warp patch 16x32)
        {
            wmma::fragment<wmma::accumulator, 16, 16, 8, float> sa[2];
            wmma::fill_fragment(sa[0], 0.f);
            wmma::fill_fragment(sa[1], 0.f);
#pragma unroll
            for (int kk = 0; kk < 8; kk++) {
                wmma::fragment<wmma::matrix_a, 16, 16, 8, wmma::precision::tf32,
                               wmma::row_major> af;
                wmma::fragment<wmma::matrix_b, 16, 16, 8, wmma::precision::tf32,
                               wmma::col_major> bf[2];
                wmma::load_matrix_sync(af, &Qs[r0 * FT_LD + kk * 8], FT_LD);
#pragma unroll
                for (int j = 0; j < 2; j++)
                    wmma::load_matrix_sync(bf[j],
                                           &Ks[cur][(c0 + j * 16) * FT_LD + kk * 8],
                                           FT_LD);
#pragma unroll
                for (int j = 0; j < 2; j++)
                    wmma::mma_sync(sa[j], af, bf[j], sa[j]);
            }
#pragma unroll
            for (int j = 0; j < 2; j++)
                wmma::store_matrix_sync(&Ss[r0 * FT_LD + c0 + j * 16], sa[j],
                                        FT_LD, wmma::mem_row_major);
        }
        __syncthreads();     // [B]

        // Online softmax: 4 threads per row, 16 cols each; rescale O row.
        {
            const int row = tid >> 2;
            const int qgrp = tid & 3;
            float* srow = &Ss[row * FT_LD + qgrp * 16];
            float rmax = -INFINITY;
#pragma unroll
            for (int c = 0; c < 16; c++) rmax = fmaxf(rmax, srow[c]);
            rmax = fmaxf(rmax, __shfl_xor_sync(0xffffffffu, rmax, 1));
            rmax = fmaxf(rmax, __shfl_xor_sync(0xffffffffu, rmax, 2));
            const float mold = m_s[row];
            const float mnew = fmaxf(mold, rmax);
            const float alpha = __expf(mold - mnew);
            float rsum = 0.f;
#pragma unroll
            for (int c = 0; c < 16; c++) {
                const float p = __expf(srow[c] - mnew);
                srow[c] = p;
                rsum += p;
            }
            rsum += __shfl_xor_sync(0xffffffffu, rsum, 1);
            rsum += __shfl_xor_sync(0xffffffffu, rsum, 2);
            if (qgrp == 0) { m_s[row] = mnew; l_s[row] = l_s[row] * alpha + rsum; }
            float* orow = &Os[row * FT_LD + qgrp * 16];
#pragma unroll
            for (int c = 0; c < 16; c++) orow[c] *= alpha;
        }
        __syncthreads();     // [C]

        // O += P @ V
        {
            wmma::fragment<wmma::accumulator, 16, 16, 8, float> oa[2];
#pragma unroll
            for (int j = 0; j < 2; j++)
                wmma::load_matrix_sync(oa[j], &Os[r0 * FT_LD + c0 + j * 16],
                                       FT_LD, wmma::mem_row_major);
#pragma unroll
            for (int kk = 0; kk < 8; kk++) {
                wmma::fragment<wmma::matrix_a, 16, 16, 8, wmma::precision::tf32,
                               wmma::row_major> pf;
                wmma::fragment<wmma::matrix_b, 16, 16, 8, wmma::precision::tf32,
                               wmma::row_major> vf[2];
                wmma::load_matrix_sync(pf, &Ss[r0 * FT_LD + kk * 8], FT_LD);
#pragma unroll
                for (int j = 0; j < 2; j++)
                    wmma::load_matrix_sync(vf[j],
                                           &Vs[cur][(kk * 8) * FT_LD + c0 + j * 16],
                                           FT_LD);
#pragma unroll
                for (int j = 0; j < 2; j++)
                    wmma::mma_sync(oa[j], pf, vf[j], oa[j]);
            }
#pragma unroll
            for (int j = 0; j < 2; j++)
                wmma::store_matrix_sync(&Os[r0 * FT_LD + c0 + j * 16], oa[j],
                                        FT_LD, wmma::mem_row_major);
        }
        // no sync here: barrier [A] of next iteration protects Ss/Os/KV reuse
    }
    __syncthreads();

    // Write out: att[b, t0+row, h*64+c] = round(O/l). 4 threads/row, 16 cols.
    {
        const int row = tid >> 2;
        const int qgrp = tid & 3;
        const float invl = 1.0f / l_s[row];
        const size_t obase = ((size_t)(b * 2048 + t0 + row)) * 1024 + h * 64 + qgrp * 16;
        const float* orow = &Os[row * FT_LD + qgrp * 16];
#pragma unroll
        for (int c4 = 0; c4 < 4; c4++) {
            float4 v = *(const float4*)(orow + c4 * 4);
            v.x = to_tf32(v.x * invl); v.y = to_tf32(v.y * invl);
            v.z = to_tf32(v.z * invl); v.w = to_tf32(v.w * invl);
            *(float4*)(out + obase + c4 * 4) = v;
        }
    }
}

// ---------------------------------------------------------------------------
// kernel_launch
// ---------------------------------------------------------------------------
extern "C" void kernel_launch(void* const* d_in, const int* in_sizes, int n_in,
                              void* d_out, int out_size) {
    const float* inputs = (const float*)d_in[0];
    const float* ln1_g  = (const float*)d_in[3];
    const float* ln1_b  = (const float*)d_in[4];
    const float* ln2_g  = (const float*)d_in[5];
    const float* ln2_b  = (const float*)d_in[6];
    const float* w_qkv  = (const float*)d_in[7];
    const float* w_out  = (const float*)d_in[8];
    const float* b_out  = (const float*)d_in[9];
    const float* w1     = (const float*)d_in[10];
    const float* b1     = (const float*)d_in[11];
    const float* w2     = (const float*)d_in[12];
    const float* b2     = (const float*)d_in[13];
    float* out = (float*)d_out;

    float *xn, *qkv, *att, *x, *hn, *h, *wqkv_r, *wout_r, *w1_r, *w2_r;
    cudaGetSymbolAddress((void**)&xn,     g_xn);
    cudaGetSymbolAddress((void**)&qkv,    g_qkv);
    cudaGetSymbolAddress((void**)&att,    g_att);
    cudaGetSymbolAddress((void**)&x,      g_x);
    cudaGetSymbolAddress((void**)&hn,     g_hn);
    cudaGetSymbolAddress((void**)&h,      g_h);
    cudaGetSymbolAddress((void**)&wqkv_r, g_wqkv_r);
    cudaGetSymbolAddress((void**)&wout_r, g_wout_r);
    cudaGetSymbolAddress((void**)&w1_r,   g_w1_r);
    cudaGetSymbolAddress((void**)&w2_r,   g_w2_r);

    cudaFuncSetAttribute(gemm_wmma<1>, cudaFuncAttributeMaxDynamicSharedMemorySize, G_SMEM);
    cudaFuncSetAttribute(gemm_wmma<2>, cudaFuncAttributeMaxDynamicSharedMemorySize, G_SMEM);
    cudaFuncSetAttribute(gemm_wmma<3>, cudaFuncAttributeMaxDynamicSharedMemorySize, G_SMEM);
    cudaFuncSetAttribute(flash_attn_tc, cudaFuncAttributeMaxDynamicSharedMemorySize, FT_SMEM);

    // 0. Pre-round weights to tf32
    round_tf32_k<<<(D_DIM * D3)    / 1024, 256>>>(w_qkv, wqkv_r);
    round_tf32_k<<<(D_DIM * D_DIM) / 1024, 256>>>(w_out, wout_r);
    round_tf32_k<<<(D_DIM * MLP_D) / 1024, 256>>>(w1, w1_r);
    round_tf32_k<<<(MLP_D * D_DIM) / 1024, 256>>>(w2, w2_r);

    // 1. x_n = round(LN1(inputs))
    ln_k<1><<<M_ROWS, 256>>>(inputs, ln1_g, ln1_b, xn);

    // 2. qkv = round(x_n @ w_qkv)   (rounded so attention can cp.async K/V)
    gemm_wmma<1><<<dim3(D3 / 128, M_ROWS / 128), 256, G_SMEM>>>(
        xn, wqkv_r, nullptr, nullptr, qkv, M_ROWS, D3, D_DIM);

    // 3. attention -> att (tf32-rounded)
    flash_attn_tc<<<dim3(32, 16, 2), 256, FT_SMEM>>>(qkv, att);

    // 4. x = att @ w_out + b_out + inputs
    gemm_wmma<2><<<dim3(D_DIM / 128, M_ROWS / 128), 256, G_SMEM>>>(
        att, wout_r, b_out, inputs, x, M_ROWS, D_DIM, D_DIM);

    // 5. h_n = round(LN2(x))
    ln_k<1><<<M_ROWS, 256>>>(x, ln2_g, ln2_b, hn);

    // 6. h = round(gelu(h_n @ w1 + b1))
    gemm_wmma<3><<<dim3(MLP_D / 128, M_ROWS / 128), 256, G_SMEM>>>(
        hn, w1_r, b1, nullptr, h, M_ROWS, MLP_D, D_DIM);

    // 7. out = h @ w2 + b2 + x
    gemm_wmma<2><<<dim3(D_DIM / 128, M_ROWS / 128), 256, G_SMEM>>>(
        h, w2_r, b2, x, out, M_ROWS, D_DIM, MLP_D);
}

// round 11
// speedup vs baseline: 1.0611x; 1.0611x over previous
#include <cuda_runtime.h>
#include <math.h>
#include <stdint.h>
#include <mma.h>

using namespace nvcuda;

// ---------------------------------------------------------------------------
// Problem constants: B=2, T=2048, D=1024, NH=16, DH=64, MLP=4096. M = 4096.
// ---------------------------------------------------------------------------
#define M_ROWS 4096
#define D_DIM  1024
#define D3     3072
#define MLP_D  4096

// Scratch (device globals; no allocation allowed)
__device__ float g_xn  [M_ROWS * D_DIM];
__device__ float g_qkv [M_ROWS * D3];
__device__ float g_att [M_ROWS * D_DIM];
__device__ float g_x   [M_ROWS * D_DIM];
__device__ float g_hn  [M_ROWS * D_DIM];
__device__ float g_h   [M_ROWS * MLP_D];
// tf32-pre-rounded weights
__device__ float g_wqkv_r[D_DIM * D3];
__device__ float g_wout_r[D_DIM * D_DIM];
__device__ float g_w1_r  [D_DIM * MLP_D];
__device__ float g_w2_r  [MLP_D * D_DIM];

__device__ __forceinline__ float to_tf32(float x) {
    float y;
    asm("cvt.rna.tf32.f32 %0, %1;" : "=f"(y) : "f"(x));
    return y;
}

// cp.async helpers
__device__ __forceinline__ void cp16(uint32_t dst, const void* src) {
    asm volatile("cp.async.cg.shared.global [%0], [%1], 16;" :: "r"(dst), "l"(src));
}
#define CP_COMMIT() asm volatile("cp.async.commit_group;" ::: "memory")
template <int N>
__device__ __forceinline__ void cp_wait() {
    asm volatile("cp.async.wait_group %0;" :: "n"(N) : "memory");
}

// ---------------------------------------------------------------------------
// Elementwise tf32 rounding (for weights). n % 1024 == 0.
// ---------------------------------------------------------------------------
__global__ void round_tf32_k(const float* __restrict__ in, float* __restrict__ out) {
    const int i = (blockIdx.x * 256 + threadIdx.x) * 4;
    float4 v = *(const float4*)(in + i);
    v.x = to_tf32(v.x); v.y = to_tf32(v.y); v.z = to_tf32(v.z); v.w = to_tf32(v.w);
    *(float4*)(out + i) = v;
}

// ---------------------------------------------------------------------------
// LayerNorm: one block (256 threads) per row of 1024 floats.
// ROUND: round output to tf32 (output feeds only GEMM A-operands).
// ---------------------------------------------------------------------------
template <int ROUND>
__global__ void ln_k(const float* __restrict__ x, const float* __restrict__ g,
                     const float* __restrict__ b, float* __restrict__ y) {
    __shared__ float rs[8], rss[8], sh[2];
    const int row = blockIdx.x;
    const int tid = threadIdx.x;
    const float4 v = *(const float4*)(x + (size_t)row * 1024 + tid * 4);
    float s  = v.x + v.y + v.z + v.w;
    float ss = v.x * v.x + v.y * v.y + v.z * v.z + v.w * v.w;
#pragma unroll
    for (int off = 16; off >= 1; off >>= 1) {
        s  += __shfl_xor_sync(0xffffffffu, s, off);
        ss += __shfl_xor_sync(0xffffffffu, ss, off);
    }
    if ((tid & 31) == 0) { rs[tid >> 5] = s; rss[tid >> 5] = ss; }
    __syncthreads();
    if (tid == 0) {
        float S = 0.f, SS = 0.f;
#pragma unroll
        for (int w = 0; w < 8; w++) { S += rs[w]; SS += rss[w]; }
        sh[0] = S * (1.0f / 1024.0f);
        sh[1] = SS * (1.0f / 1024.0f);
    }
    __syncthreads();
    const float mu   = sh[0];
    const float var  = sh[1] - mu * mu;
    const float rstd = rsqrtf(var + 1e-5f);
    const float4 gg = *(const float4*)(g + tid * 4);
    const float4 bb = *(const float4*)(b + tid * 4);
    float4 o;
    o.x = (v.x - mu) * rstd * gg.x + bb.x;
    o.y = (v.y - mu) * rstd * gg.y + bb.y;
    o.z = (v.z - mu) * rstd * gg.z + bb.z;
    o.w = (v.w - mu) * rstd * gg.w + bb.w;
    if (ROUND) {
        o.x = to_tf32(o.x); o.y = to_tf32(o.y); o.z = to_tf32(o.z); o.w = to_tf32(o.w);
    }
    *(float4*)(y + (size_t)row * 1024 + tid * 4) = o;
}

// ---------------------------------------------------------------------------
// WMMA tf32 GEMM, 2-stage cp.async, ONE syncthreads per K-iteration.
// (2 stages keeps smem at 70.7KB -> 2 CTAs/SM; reuse distance 2 makes the
//  post-barrier prefetch into slot (kt+1)&1 safe.)
// C[M,N] = A[M,K] @ B[K,N] (+ epilogue). A, B tf32-pre-rounded.
//   EPI 0: none  1: round_tf32  2: +bias+res  3: round_tf32(gelu(.+bias))
// CTA tile 128x128, BK=32, 256 threads, 8 warps, warp tile 32x64.
// ---------------------------------------------------------------------------
#define G_AS_LD 36
#define G_BS_LD 132
#define G_STG_FLOATS (128 * G_AS_LD + 32 * G_BS_LD)   // 8832
#define G_EP_LD 68
#define G_SMEM (2 * G_STG_FLOATS * 4)                 // 70656 B (epi 17408 fl fits)

__device__ __forceinline__ void g_load_stage(
    const float* __restrict__ A, const float* __restrict__ B,
    int N, int K, int m0, int n0, int k0, float* As, float* Bs, int tid) {
#pragma unroll
    for (int v = 0; v < 4; v++) {
        const int id = v * 256 + tid;
        const int r  = id >> 3;
        const int c4 = (id & 7) * 4;
        cp16((uint32_t)__cvta_generic_to_shared(&As[r * G_AS_LD + c4]),
             A + (size_t)(m0 + r) * K + k0 + c4);
    }
#pragma unroll
    for (int v = 0; v < 4; v++) {
        const int id = v * 256 + tid;
        const int r  = id >> 5;
        const int c4 = (id & 31) * 4;
        cp16((uint32_t)__cvta_generic_to_shared(&Bs[r * G_BS_LD + c4]),
             B + (size_t)(k0 + r) * N + n0 + c4);
    }
}

template <int EPI>
__global__ __launch_bounds__(256, 2)
void gemm_wmma(const float* __restrict__ A, const float* __restrict__ B,
               const float* __restrict__ bias, const float* __restrict__ res,
               float* __restrict__ C, int M, int N, int K) {
    extern __shared__ float sm[];
    float* As[2] = {sm, sm + G_STG_FLOATS};
    float* Bs[2] = {sm + 128 * G_AS_LD, sm + G_STG_FLOATS + 128 * G_AS_LD};

    const int tid  = threadIdx.x;
    const int wid  = tid >> 5;
    const int lane = tid & 31;
    const int m0 = blockIdx.y * 128;
    const int n0 = blockIdx.x * 128;
    const int wm = (wid & 3) * 32;
    const int wn = (wid >> 2) * 64;

    wmma::fragment<wmma::accumulator, 16, 16, 8, float> acc[2][4];
#pragma unroll
    for (int i = 0; i < 2; i++)
#pragma unroll
        for (int j = 0; j < 4; j++)
            wmma::fill_fragment(acc[i][j], 0.0f);

    const int NK = K / 32;
    g_load_stage(A, B, N, K, m0, n0, 0, As[0], Bs[0], tid);
    CP_COMMIT();

    for (int kt = 0; kt < NK; kt++) {
        cp_wait<0>();        // stage kt resident
        __syncthreads();     // single barrier: also retires readers of slot kt^1

        // prefetch stage kt+1 into the other slot (its readers finished in
        // iteration kt-1, before the barrier above)
        if (kt + 1 < NK) {
            g_load_stage(A, B, N, K, m0, n0, (kt + 1) * 32,
                         As[(kt + 1) & 1], Bs[(kt + 1) & 1], tid);
            CP_COMMIT();
        }

        const float* as = As[kt & 1];
        const float* bs = Bs[kt & 1];
#pragma unroll
        for (int kk = 0; kk < 4; kk++) {
            wmma::fragment<wmma::matrix_a, 16, 16, 8, wmma::precision::tf32,
                           wmma::row_major> af[2];
            wmma::fragment<wmma::matrix_b, 16, 16, 8, wmma::precision::tf32,
                           wmma::row_major> bf[4];
#pragma unroll
            for (int i = 0; i < 2; i++)
                wmma::load_matrix_sync(af[i], &as[(wm + i * 16) * G_AS_LD + kk * 8],
                                       G_AS_LD);
#pragma unroll
            for (int j = 0; j < 4; j++)
                wmma::load_matrix_sync(bf[j], &bs[(kk * 8) * G_BS_LD + wn + j * 16],
                                       G_BS_LD);
#pragma unroll
            for (int i = 0; i < 2; i++)
#pragma unroll
                for (int j = 0; j < 4; j++)
                    wmma::mma_sync(acc[i][j], af[i], bf[j], acc[i][j]);
        }
    }
    __syncthreads();   // protect stage smem before epilogue reuse

    // Epilogue: warp-private smem patch, then coalesced global write.
    float* ep = sm + wid * (32 * G_EP_LD);
#pragma unroll
    for (int i = 0; i < 2; i++)
#pragma unroll
        for (int j = 0; j < 4; j++)
            wmma::store_matrix_sync(&ep[(i * 16) * G_EP_LD + j * 16], acc[i][j],
                                    G_EP_LD, wmma::mem_row_major);
    __syncwarp();

#pragma unroll 4
    for (int r = 0; r < 32; r++) {
        const int m = m0 + wm + r;
#pragma unroll
        for (int cc = 0; cc < 2; cc++) {
            const int c = lane + cc * 32;
            const int n = n0 + wn + c;
            float v = ep[r * G_EP_LD + c];
            if (EPI == 2 || EPI == 3) v += bias[n];
            if (EPI == 2) v += res[(size_t)m * N + n];
            if (EPI == 3) v = 0.5f * v * (1.0f + erff(v * 0.7071067811865476f));
            if (EPI == 1 || EPI == 3) v = to_tf32(v);
            C[(size_t)m * N + n] = v;
        }
    }
}

// ---------------------------------------------------------------------------
// Tensor-core flash attention: cp.async double-buffered K/V, Q in registers.
// 256 threads (8 warps), 64 q-rows x one head x one batch.
// Smem: S, O, K0, V0, K1, V1 (64x68 each) + m/l = 104.96 KB -> 2 CTAs/SM.
// Q is staged through the S region once, extracted to matrix_a fragments.
// 3 syncthreads per k-tile; K/V of kt+1 prefetched during compute of kt.
// ---------------------------------------------------------------------------
#define FT_LD 68
#define FT_T  (64 * FT_LD)
#define FT_SMEM ((6 * FT_T + 128) * 4)   // 104960 B

__device__ __forceinline__ void fa_load_kv(const float* __restrict__ kvbase, int kt,
                                           float* K, float* V, int tid) {
    const float* kb = kvbase + (size_t)(kt * 64) * 3072;
#pragma unroll
    for (int v = 0; v < 4; v++) {
        const int id = v * 256 + tid;
        const int r  = id >> 4;
        const int c4 = (id & 15) * 4;
        cp16((uint32_t)__cvta_generic_to_shared(&K[r * FT_LD + c4]),
             kb + (size_t)r * 3072 + c4);
        cp16((uint32_t)__cvta_generic_to_shared(&V[r * FT_LD + c4]),
             kb + 1024 + (size_t)r * 3072 + c4);
    }
}

__global__ __launch_bounds__(256, 2)
void flash_attn_tc(const float* __restrict__ qkv, float* __restrict__ out) {
    extern __shared__ float sm[];
    float* Ss = sm;                       // also Q staging before the loop
    float* Os = sm + FT_T;
    float* Ks[2] = {sm + 2 * FT_T, sm + 4 * FT_T};
    float* Vs[2] = {sm + 3 * FT_T, sm + 5 * FT_T};
    float* m_s = sm + 6 * FT_T;
    float* l_s = m_s + 64;

    const int qt = blockIdx.x;
    const int h  = blockIdx.y;
    const int b  = blockIdx.z;
    const int tid  = threadIdx.x;
    const int wid  = tid >> 5;
    const int r0 = (wid & 3) * 16;
    const int c0 = (wid >> 2) * 32;
    const int t0 = qt * 64;

    const float* kvbase = qkv + ((size_t)(b * 2048)) * 3072 + 1024 + h * 64;

    // Prefetch K/V tile 0
    fa_load_kv(kvbase, 0, Ks[0], Vs[0], tid);
    CP_COMMIT();

    // Stage Q (scaled by 1/8 exact, tf32-rounded) into S region; zero O.
    const float* qbase = qkv + ((size_t)(b * 2048 + t0)) * 3072 + h * 64;
#pragma unroll
    for (int v = 0; v < 4; v++) {
        const int id = v * 256 + tid;
        const int r  = id >> 4;
        const int c4 = (id & 15) * 4;
        float4 x = *(const float4*)(qbase + (size_t)r * 3072 + c4);
        x.x = to_tf32(x.x * 0.125f); x.y = to_tf32(x.y * 0.125f);
        x.z = to_tf32(x.z * 0.125f); x.w = to_tf32(x.w * 0.125f);
        *(float4*)&Ss[r * FT_LD + c4] = x;
        *(float4*)&Os[r * FT_LD + c4] = make_float4(0.f, 0.f, 0.f, 0.f);
    }
    if (tid < 64) { m_s[tid] = -INFINITY; l_s[tid] = 0.f; }
    __syncthreads();

    // Extract this warp's Q fragments (rows r0..r0+15, all 8 k-steps).
    wmma::fragment<wmma::matrix_a, 16, 16, 8, wmma::precision::tf32,
                   wmma::row_major> qf[8];
#pragma unroll
    for (int kk = 0; kk < 8; kk++)
        wmma::load_matrix_sync(qf[kk], &Ss[r0 * FT_LD + kk * 8], FT_LD);
    // (no sync needed: first overwrite of Ss happens after barrier [A] below)

    for (int kt = 0; kt < 32; kt++) {
        const int cur = kt & 1;
        cp_wait<0>();        // K/V tile kt resident
        __syncthreads();     // [A] KV visible; P@V of kt-1 done everywhere

        if (kt + 1 < 32) {
            fa_load_kv(kvbase, kt + 1, Ks[cur ^ 1], Vs[cur ^ 1], tid);
            CP_COMMIT();
        }

        // S = Q @ K^T  (warp patch 16x32; Q from registers)
        {
            wmma::fragment<wmma::accumulator, 16, 16, 8, float> sa[2];
            wmma::fill_fragment(sa[0], 0.f);
            wmma::fill_fragment(sa[1], 0.f);
#pragma unroll
            for (int kk = 0; kk < 8; kk++) {
                wmma::fragment<wmma::matrix_b, 16, 16, 8, wmma::precision::tf32,
                               wmma::col_major> bf[2];
#pragma unroll
                for (int j = 0; j < 2; j++)
                    wmma::load_matrix_sync(bf[j],
                                           &Ks[cur][(c0 + j * 16) * FT_LD + kk * 8],
                                           FT_LD);
#pragma unroll
                for (int j = 0; j < 2; j++)
                    wmma::mma_sync(sa[j], qf[kk], bf[j], sa[j]);
            }
#pragma unroll
            for (int j = 0; j < 2; j++)
                wmma::store_matrix_sync(&Ss[r0 * FT_LD + c0 + j * 16], sa[j],
                                        FT_LD, wmma::mem_row_major);
        }
        __syncthreads();     // [B]

        // Online softmax: 4 threads per row, 16 cols each; rescale O row.
        {
            const int row = tid >> 2;
            const int qgrp = tid & 3;
            float* srow = &Ss[row * FT_LD + qgrp * 16];
            float rmax = -INFINITY;
#pragma unroll
            for (int c = 0; c < 16; c++) rmax = fmaxf(rmax, srow[c]);
            rmax = fmaxf(rmax, __shfl_xor_sync(0xffffffffu, rmax, 1));
            rmax = fmaxf(rmax, __shfl_xor_sync(0xffffffffu, rmax, 2));
            const float mold = m_s[row];
            const float mnew = fmaxf(mold, rmax);
            const float alpha = __expf(mold - mnew);
            float rsum = 0.f;
#pragma unroll
            for (int c = 0; c < 16; c++) {
                const float p = __expf(srow[c] - mnew);
                srow[c] = p;
                rsum += p;
            }
            rsum += __shfl_xor_sync(0xffffffffu, rsum, 1);
            rsum += __shfl_xor_sync(0xffffffffu, rsum, 2);
            if (qgrp == 0) { m_s[row] = mnew; l_s[row] = l_s[row] * alpha + rsum; }
            float* orow = &Os[row * FT_LD + qgrp * 16];
#pragma unroll
            for (int c = 0; c < 16; c++) orow[c] *= alpha;
        }
        __syncthreads();     // [C]

        // O += P @ V
        {
            wmma::fragment<wmma::accumulator, 16, 16, 8, float> oa[2];
#pragma unroll
            for (int j = 0; j < 2; j++)
                wmma::load_matrix_sync(oa[j], &Os[r0 * FT_LD + c0 + j * 16],
                                       FT_LD, wmma::mem_row_major);
#pragma unroll
            for (int kk = 0; kk < 8; kk++) {
                wmma::fragment<wmma::matrix_a, 16, 16, 8, wmma::precision::tf32,
                               wmma::row_major> pf;
                wmma::fragment<wmma::matrix_b, 16, 16, 8, wmma::precision::tf32,
                               wmma::row_major> vf[2];
                wmma::load_matrix_sync(pf, &Ss[r0 * FT_LD + kk * 8], FT_LD);
#pragma unroll
                for (int j = 0; j < 2; j++)
                    wmma::load_matrix_sync(vf[j],
                                           &Vs[cur][(kk * 8) * FT_LD + c0 + j * 16],
                                           FT_LD);
#pragma unroll
                for (int j = 0; j < 2; j++)
                    wmma::mma_sync(oa[j], pf, vf[j], oa[j]);
            }
#pragma unroll
            for (int j = 0; j < 2; j++)
                wmma::store_matrix_sync(&Os[r0 * FT_LD + c0 + j * 16], oa[j],
                                        FT_LD, wmma::mem_row_major);
        }
        // no trailing sync: barrier [A] of next iteration protects reuse
    }
    __syncthreads();

    // Write out: att[b, t0+row, h*64+c] = round(O/l). 4 threads/row, 16 cols.
    {
        const int row = tid >> 2;
        const int qgrp = tid & 3;
        const float invl = 1.0f / l_s[row];
        const size_t obase = ((size_t)(b * 2048 + t0 + row)) * 1024 + h * 64 + qgrp * 16;
        const float* orow = &Os[row * FT_LD + qgrp * 16];
#pragma unroll
        for (int c4 = 0; c4 < 4; c4++) {
            float4 v = *(const float4*)(orow + c4 * 4);
            v.x = to_tf32(v.x * invl); v.y = to_tf32(v.y * invl);
            v.z = to_tf32(v.z * invl); v.w = to_tf32(v.w * invl);
            *(float4*)(out + obase + c4 * 4) = v;
        }
    }
}

// ---------------------------------------------------------------------------
// kernel_launch
// ---------------------------------------------------------------------------
extern "C" void kernel_launch(void* const* d_in, const int* in_sizes, int n_in,
                              void* d_out, int out_size) {
    const float* inputs = (const float*)d_in[0];
    const float* ln1_g  = (const float*)d_in[3];
    const float* ln1_b  = (const float*)d_in[4];
    const float* ln2_g  = (const float*)d_in[5];
    const float* ln2_b  = (const float*)d_in[6];
    const float* w_qkv  = (const float*)d_in[7];
    const float* w_out  = (const float*)d_in[8];
    const float* b_out  = (const float*)d_in[9];
    const float* w1     = (const float*)d_in[10];
    const float* b1     = (const float*)d_in[11];
    const float* w2     = (const float*)d_in[12];
    const float* b2     = (const float*)d_in[13];
    float* out = (float*)d_out;

    float *xn, *qkv, *att, *x, *hn, *h, *wqkv_r, *wout_r, *w1_r, *w2_r;
    cudaGetSymbolAddress((void**)&xn,     g_xn);
    cudaGetSymbolAddress((void**)&qkv,    g_qkv);
    cudaGetSymbolAddress((void**)&att,    g_att);
    cudaGetSymbolAddress((void**)&x,      g_x);
    cudaGetSymbolAddress((void**)&hn,     g_hn);
    cudaGetSymbolAddress((void**)&h,      g_h);
    cudaGetSymbolAddress((void**)&wqkv_r, g_wqkv_r);
    cudaGetSymbolAddress((void**)&wout_r, g_wout_r);
    cudaGetSymbolAddress((void**)&w1_r,   g_w1_r);
    cudaGetSymbolAddress((void**)&w2_r,   g_w2_r);

    cudaFuncSetAttribute(gemm_wmma<1>, cudaFuncAttributeMaxDynamicSharedMemorySize, G_SMEM);
    cudaFuncSetAttribute(gemm_wmma<2>, cudaFuncAttributeMaxDynamicSharedMemorySize, G_SMEM);
    cudaFuncSetAttribute(gemm_wmma<3>, cudaFuncAttributeMaxDynamicSharedMemorySize, G_SMEM);
    cudaFuncSetAttribute(flash_attn_tc, cudaFuncAttributeMaxDynamicSharedMemorySize, FT_SMEM);

    // 0. Pre-round weights to tf32
    round_tf32_k<<<(D_DIM * D3)    / 1024, 256>>>(w_qkv, wqkv_r);
    round_tf32_k<<<(D_DIM * D_DIM) / 1024, 256>>>(w_out, wout_r);
    round_tf32_k<<<(D_DIM * MLP_D) / 1024, 256>>>(w1, w1_r);
    round_tf32_k<<<(MLP_D * D_DIM) / 1024, 256>>>(w2, w2_r);

    // 1. x_n = round(LN1(inputs))
    ln_k<1><<<M_ROWS, 256>>>(inputs, ln1_g, ln1_b, xn);

    // 2. qkv = round(x_n @ w_qkv)
    gemm_wmma<1><<<dim3(D3 / 128, M_ROWS / 128), 256, G_SMEM>>>(
        xn, wqkv_r, nullptr, nullptr, qkv, M_ROWS, D3, D_DIM);

    // 3. attention -> att (tf32-rounded)
    flash_attn_tc<<<dim3(32, 16, 2), 256, FT_SMEM>>>(qkv, att);

    // 4. x = att @ w_out + b_out + inputs
    gemm_wmma<2><<<dim3(D_DIM / 128, M_ROWS / 128), 256, G_SMEM>>>(
        att, wout_r, b_out, inputs, x, M_ROWS, D_DIM, D_DIM);

    // 5. h_n = round(LN2(x))
    ln_k<1><<<M_ROWS, 256>>>(x, ln2_g, ln2_b, hn);

    // 6. h = round(gelu(h_n @ w1 + b1))
    gemm_wmma<3><<<dim3(MLP_D / 128, M_ROWS / 128), 256, G_SMEM>>>(
        hn, w1_r, b1, nullptr, h, M_ROWS, MLP_D, D_DIM);

    // 7. out = h @ w2 + b2 + x
    gemm_wmma<2><<<dim3(D_DIM / 128, M_ROWS / 128), 256, G_SMEM>>>(
        h, w2_r, b2, x, out, M_ROWS, D_DIM, MLP_D);
}

// round 14
// speedup vs baseline: 2.2990x; 2.1666x over previous
#include <cuda_runtime.h>
#include <cuda_fp16.h>
#include <math.h>
#include <stdint.h>
#include <mma.h>

using namespace nvcuda;
typedef __half f16;

// ---------------------------------------------------------------------------
// Problem constants: B=2, T=2048, D=1024, NH=16, DH=64, MLP=4096. M = 4096.
// ---------------------------------------------------------------------------
#define M_ROWS 4096
#define D_DIM  1024
#define D3     3072
#define MLP_D  4096

// Scratch (device globals; no allocation allowed)
__device__ f16   g_xn  [M_ROWS * D_DIM];   // LN1 out (fp16, GEMM A)
__device__ f16   g_qkv [M_ROWS * D3];      // qkv (fp16, attention operands)
__device__ f16   g_att [M_ROWS * D_DIM];   // attention out (fp16, GEMM A)
__device__ float g_x   [M_ROWS * D_DIM];   // residual-1 (fp32)
__device__ f16   g_hn  [M_ROWS * D_DIM];   // LN2 out (fp16)
__device__ f16   g_h   [M_ROWS * MLP_D];   // gelu out (fp16)
// fp16 weights
__device__ f16 g_wqkv_h[D_DIM * D3];
__device__ f16 g_wout_h[D_DIM * D_DIM];
__device__ f16 g_w1_h  [D_DIM * MLP_D];
__device__ f16 g_w2_h  [MLP_D * D_DIM];

// cp.async helpers
__device__ __forceinline__ void cp16(uint32_t dst, const void* src) {
    asm volatile("cp.async.cg.shared.global [%0], [%1], 16;" :: "r"(dst), "l"(src));
}
#define CP_COMMIT() asm volatile("cp.async.commit_group;" ::: "memory")
template <int N>
__device__ __forceinline__ void cp_wait() {
    asm volatile("cp.async.wait_group %0;" :: "n"(N) : "memory");
}

// ---------------------------------------------------------------------------
// fp32 -> fp16 conversion (weights). n % 1024 == 0.
// ---------------------------------------------------------------------------
__global__ void cvt_f16_k(const float* __restrict__ in, f16* __restrict__ out) {
    const int i = (blockIdx.x * 256 + threadIdx.x) * 4;
    const float4 v = *(const float4*)(in + i);
    f16 o[4] = {__float2half_rn(v.x), __float2half_rn(v.y),
                __float2half_rn(v.z), __float2half_rn(v.w)};
    *(uint64_t*)(out + i) = *(uint64_t*)o;
}

// ---------------------------------------------------------------------------
// LayerNorm: one block (256 threads) per row of 1024 floats -> fp16 out.
// ---------------------------------------------------------------------------
__global__ void ln_f16_k(const float* __restrict__ x, const float* __restrict__ g,
                         const float* __restrict__ b, f16* __restrict__ y) {
    __shared__ float rs[8], rss[8], sh[2];
    const int row = blockIdx.x;
    const int tid = threadIdx.x;
    const float4 v = *(const float4*)(x + (size_t)row * 1024 + tid * 4);
    float s  = v.x + v.y + v.z + v.w;
    float ss = v.x * v.x + v.y * v.y + v.z * v.z + v.w * v.w;
#pragma unroll
    for (int off = 16; off >= 1; off >>= 1) {
        s  += __shfl_xor_sync(0xffffffffu, s, off);
        ss += __shfl_xor_sync(0xffffffffu, ss, off);
    }
    if ((tid & 31) == 0) { rs[tid >> 5] = s; rss[tid >> 5] = ss; }
    __syncthreads();
    if (tid == 0) {
        float S = 0.f, SS = 0.f;
#pragma unroll
        for (int w = 0; w < 8; w++) { S += rs[w]; SS += rss[w]; }
        sh[0] = S * (1.0f / 1024.0f);
        sh[1] = SS * (1.0f / 1024.0f);
    }
    __syncthreads();
    const float mu   = sh[0];
    const float var  = sh[1] - mu * mu;
    const float rstd = rsqrtf(var + 1e-5f);
    const float4 gg = *(const float4*)(g + tid * 4);
    const float4 bb = *(const float4*)(b + tid * 4);
    f16 o[4];
    o[0] = __float2half_rn((v.x - mu) * rstd * gg.x + bb.x);
    o[1] = __float2half_rn((v.y - mu) * rstd * gg.y + bb.y);
    o[2] = __float2half_rn((v.z - mu) * rstd * gg.z + bb.z);
    o[3] = __float2half_rn((v.w - mu) * rstd * gg.w + bb.w);
    *(uint64_t*)(y + (size_t)row * 1024 + tid * 4) = *(uint64_t*)o;
}

// ---------------------------------------------------------------------------
// WMMA fp16 GEMM (fp32 accum), 2-stage cp.async, ONE syncthreads / K-iter.
// C[M,N] = A[M,K] @ B[K,N] (+ epilogue). A, B fp16.
//   EPI 0: C fp16             (qkv)
//   EPI 2: C fp32 = +bias+res (wout, w2)
//   EPI 3: C fp16 = gelu(.+bias) (mlp1)
// CTA tile 128x128, BK=32, 256 threads, 8 warps, warp tile 32x64.
// ---------------------------------------------------------------------------
#define GB_AS_LD 40
#define GB_BS_LD 136
#define GB_STG (128 * GB_AS_LD + 32 * GB_BS_LD)   // 9472 f16 elems / stage
#define G_EP_LD 68
#define G_SMEM (8 * 32 * G_EP_LD * 4)             // 69632 B (> 2*9472*2=37888)

__device__ __forceinline__ void g_load_stage(
    const f16* __restrict__ A, const f16* __restrict__ B,
    int N, int K, int m0, int n0, int k0, f16* As, f16* Bs, int tid) {
#pragma unroll
    for (int v = 0; v < 2; v++) {
        const int id = v * 256 + tid;
        const int r  = id >> 2;          // 4 slots per 32-elem A row
        const int s  = (id & 3) * 8;
        cp16((uint32_t)__cvta_generic_to_shared(&As[r * GB_AS_LD + s]),
             A + (size_t)(m0 + r) * K + k0 + s);
    }
#pragma unroll
    for (int v = 0; v < 2; v++) {
        const int id = v * 256 + tid;
        const int r  = id >> 4;          // 16 slots per 128-elem B row
        const int s  = (id & 15) * 8;
        cp16((uint32_t)__cvta_generic_to_shared(&Bs[r * GB_BS_LD + s]),
             B + (size_t)(k0 + r) * N + n0 + s);
    }
}

template <int EPI>
__global__ __launch_bounds__(256, 2)
void gemm_hf(const f16* __restrict__ A, const f16* __restrict__ B,
             const float* __restrict__ bias, const float* __restrict__ res,
             void* __restrict__ Cv, int M, int N, int K) {
    extern __shared__ char smc[];
    f16* As[2] = {(f16*)smc, (f16*)smc + GB_STG};
    f16* Bs[2] = {(f16*)smc + 128 * GB_AS_LD, (f16*)smc + GB_STG + 128 * GB_AS_LD};

    const int tid  = threadIdx.x;
    const int wid  = tid >> 5;
    const int lane = tid & 31;
    const int m0 = blockIdx.y * 128;
    const int n0 = blockIdx.x * 128;
    const int wm = (wid & 3) * 32;
    const int wn = (wid >> 2) * 64;

    wmma::fragment<wmma::accumulator, 16, 16, 16, float> acc[2][4];
#pragma unroll
    for (int i = 0; i < 2; i++)
#pragma unroll
        for (int j = 0; j < 4; j++)
            wmma::fill_fragment(acc[i][j], 0.0f);

    const int NK = K / 32;
    g_load_stage(A, B, N, K, m0, n0, 0, As[0], Bs[0], tid);
    CP_COMMIT();

    for (int kt = 0; kt < NK; kt++) {
        cp_wait<0>();
        __syncthreads();   // stage kt visible; slot kt^1 readers retired

        if (kt + 1 < NK) {
            g_load_stage(A, B, N, K, m0, n0, (kt + 1) * 32,
                         As[(kt + 1) & 1], Bs[(kt + 1) & 1], tid);
            CP_COMMIT();
        }

        const f16* as = As[kt & 1];
        const f16* bs = Bs[kt & 1];
#pragma unroll
        for (int kk = 0; kk < 2; kk++) {
            wmma::fragment<wmma::matrix_a, 16, 16, 16, f16, wmma::row_major> af[2];
            wmma::fragment<wmma::matrix_b, 16, 16, 16, f16, wmma::row_major> bf_[4];
#pragma unroll
            for (int i = 0; i < 2; i++)
                wmma::load_matrix_sync(af[i], &as[(wm + i * 16) * GB_AS_LD + kk * 16],
                                       GB_AS_LD);
#pragma unroll
            for (int j = 0; j < 4; j++)
                wmma::load_matrix_sync(bf_[j], &bs[(kk * 16) * GB_BS_LD + wn + j * 16],
                                       GB_BS_LD);
#pragma unroll
            for (int i = 0; i < 2; i++)
#pragma unroll
                for (int j = 0; j < 4; j++)
                    wmma::mma_sync(acc[i][j], af[i], bf_[j], acc[i][j]);
        }
    }
    __syncthreads();   // protect stage smem before epilogue reuse

    // Epilogue: warp-private fp32 smem patch, then coalesced global write.
    float* ep = (float*)smc + wid * (32 * G_EP_LD);
#pragma unroll
    for (int i = 0; i < 2; i++)
#pragma unroll
        for (int j = 0; j < 4; j++)
            wmma::store_matrix_sync(&ep[(i * 16) * G_EP_LD + j * 16], acc[i][j],
                                    G_EP_LD, wmma::mem_row_major);
    __syncwarp();

#pragma unroll 4
    for (int r = 0; r < 32; r++) {
        const int m = m0 + wm + r;
#pragma unroll
        for (int cc = 0; cc < 2; cc++) {
            const int c = lane + cc * 32;
            const int n = n0 + wn + c;
            float v = ep[r * G_EP_LD + c];
            if (EPI == 2 || EPI == 3) v += bias[n];
            if (EPI == 2) v += res[(size_t)m * N + n];
            if (EPI == 3) v = 0.5f * v * (1.0f + erff(v * 0.7071067811865476f));
            if (EPI == 2) ((float*)Cv)[(size_t)m * N + n] = v;
            else          ((f16*)Cv)[(size_t)m * N + n] = __float2half_rn(v);
        }
    }
}

// ---------------------------------------------------------------------------
// fp16 tensor-core flash attention; fp32 softmax & O accumulation.
// 256 threads (8 warps), 64 q-rows x one head x one batch.
// cp.async double-buffered fp16 K/V; Q fragments in registers.
// Smem bytes: Ss(17408) Os(17408) Ph(9216, also Q staging) K0 V0 K1 V1
// (9216 each) + m/l -> 81408 B -> 2 CTAs/SM.
// ---------------------------------------------------------------------------
#define FB_LDF 68                       // fp32 tile ld (S, O)
#define FB_LDB 72                       // fp16 tile ld (Q, P, K, V)
#define FB_SS  0
#define FB_OS  17408
#define FB_PB  34816
#define FB_K0  44032
#define FB_V0  53248
#define FB_K1  62464
#define FB_V1  71680
#define FB_ML  80896
#define FB_SMEM (FB_ML + 512)

__device__ __forceinline__ void fa_load_kv(const f16* __restrict__ kvbase, int kt,
                                           f16* K, f16* V, int tid) {
    const f16* kb = kvbase + (size_t)(kt * 64) * 3072;
#pragma unroll
    for (int v = 0; v < 2; v++) {
        const int id = v * 256 + tid;
        const int r  = id >> 3;         // 8 slots per 64-elem row
        const int s  = (id & 7) * 8;
        cp16((uint32_t)__cvta_generic_to_shared(&K[r * FB_LDB + s]),
             kb + (size_t)r * 3072 + s);
        cp16((uint32_t)__cvta_generic_to_shared(&V[r * FB_LDB + s]),
             kb + 1024 + (size_t)r * 3072 + s);
    }
}

__global__ __launch_bounds__(256, 2)
void flash_attn_hf(const f16* __restrict__ qkv, f16* __restrict__ out) {
    extern __shared__ char smc[];
    float* Ss = (float*)(smc + FB_SS);
    float* Os = (float*)(smc + FB_OS);
    f16*   Ph = (f16*)(smc + FB_PB);    // also Q staging before the loop
    f16*   Ks[2] = {(f16*)(smc + FB_K0), (f16*)(smc + FB_K1)};
    f16*   Vs[2] = {(f16*)(smc + FB_V0), (f16*)(smc + FB_V1)};
    float* m_s = (float*)(smc + FB_ML);
    float* l_s = m_s + 64;

    const int qt = blockIdx.x;
    const int h  = blockIdx.y;
    const int b  = blockIdx.z;
    const int tid  = threadIdx.x;
    const int wid  = tid >> 5;
    const int r0 = (wid & 3) * 16;
    const int c0 = (wid >> 2) * 32;
    const int t0 = qt * 64;

    const f16* kvbase = qkv + ((size_t)(b * 2048)) * 3072 + 1024 + h * 64;

    // Prefetch K/V tile 0
    fa_load_kv(kvbase, 0, Ks[0], Vs[0], tid);
    CP_COMMIT();

    // Stage Q (x0.125 — exact power of two in fp16).
    const f16* qbase = qkv + ((size_t)(b * 2048 + t0)) * 3072 + h * 64;
#pragma unroll
    for (int v = 0; v < 2; v++) {
        const int id = v * 256 + tid;
        const int r  = id >> 3;
        const int s  = (id & 7) * 8;
        f16 q8[8];
        *(uint4*)q8 = *(const uint4*)(qbase + (size_t)r * 3072 + s);
#pragma unroll
        for (int u = 0; u < 8; u++)
            q8[u] = __float2half_rn(__half2float(q8[u]) * 0.125f);
        *(uint4*)&Ph[r * FB_LDB + s] = *(uint4*)q8;
    }
    for (int i = tid; i < 64 * FB_LDF; i += 256) Os[i] = 0.f;
    if (tid < 64) { m_s[tid] = -INFINITY; l_s[tid] = 0.f; }
    __syncthreads();

    // Extract this warp's Q fragments (rows r0..r0+15, 4 k-steps of 16).
    wmma::fragment<wmma::matrix_a, 16, 16, 16, f16, wmma::row_major> qf[4];
#pragma unroll
    for (int kk = 0; kk < 4; kk++)
        wmma::load_matrix_sync(qf[kk], &Ph[r0 * FB_LDB + kk * 16], FB_LDB);
    // first overwrite of Ph is in softmax of kt=0, after barriers [A]+[B]

    for (int kt = 0; kt < 32; kt++) {
        const int cur = kt & 1;
        cp_wait<0>();
        __syncthreads();     // [A] K/V(kt) visible; P@V(kt-1) retired

        if (kt + 1 < 32) {
            fa_load_kv(kvbase, kt + 1, Ks[cur ^ 1], Vs[cur ^ 1], tid);
            CP_COMMIT();
        }

        // S = Q @ K^T  (warp patch 16x32)
        {
            wmma::fragment<wmma::accumulator, 16, 16, 16, float> sa[2];
            wmma::fill_fragment(sa[0], 0.f);
            wmma::fill_fragment(sa[1], 0.f);
#pragma unroll
            for (int kk = 0; kk < 4; kk++) {
                wmma::fragment<wmma::matrix_b, 16, 16, 16, f16,
                               wmma::col_major> kf[2];
#pragma unroll
                for (int j = 0; j < 2; j++)
                    wmma::load_matrix_sync(kf[j],
                                           &Ks[cur][(c0 + j * 16) * FB_LDB + kk * 16],
                                           FB_LDB);
#pragma unroll
                for (int j = 0; j < 2; j++)
                    wmma::mma_sync(sa[j], qf[kk], kf[j], sa[j]);
            }
#pragma unroll
            for (int j = 0; j < 2; j++)
                wmma::store_matrix_sync(&Ss[r0 * FB_LDF + c0 + j * 16], sa[j],
                                        FB_LDF, wmma::mem_row_major);
        }
        __syncthreads();     // [B]

        // Online softmax: 4 threads/row, 16 cols each; P -> fp16; rescale O.
        {
            const int row = tid >> 2;
            const int qgrp = tid & 3;
            const float* srow = &Ss[row * FB_LDF + qgrp * 16];
            f16* prow = &Ph[row * FB_LDB + qgrp * 16];
            float rmax = -INFINITY;
#pragma unroll
            for (int c = 0; c < 16; c++) rmax = fmaxf(rmax, srow[c]);
            rmax = fmaxf(rmax, __shfl_xor_sync(0xffffffffu, rmax, 1));
            rmax = fmaxf(rmax, __shfl_xor_sync(0xffffffffu, rmax, 2));
            const float mold = m_s[row];
            const float mnew = fmaxf(mold, rmax);
            const float alpha = __expf(mold - mnew);
            float rsum = 0.f;
#pragma unroll
            for (int c = 0; c < 16; c++) {
                const float p = __expf(srow[c] - mnew);
                prow[c] = __float2half_rn(p);
                rsum += p;
            }
            rsum += __shfl_xor_sync(0xffffffffu, rsum, 1);
            rsum += __shfl_xor_sync(0xffffffffu, rsum, 2);
            if (qgrp == 0) { m_s[row] = mnew; l_s[row] = l_s[row] * alpha + rsum; }
            float* orow = &Os[row * FB_LDF + qgrp * 16];
#pragma unroll
            for (int c = 0; c < 16; c++) orow[c] *= alpha;
        }
        __syncthreads();     // [C]

        // O += P @ V
        {
            wmma::fragment<wmma::accumulator, 16, 16, 16, float> oa[2];
#pragma unroll
            for (int j = 0; j < 2; j++)
                wmma::load_matrix_sync(oa[j], &Os[r0 * FB_LDF + c0 + j * 16],
                                       FB_LDF, wmma::mem_row_major);
#pragma unroll
            for (int kk = 0; kk < 4; kk++) {
                wmma::fragment<wmma::matrix_a, 16, 16, 16, f16,
                               wmma::row_major> pf;
                wmma::fragment<wmma::matrix_b, 16, 16, 16, f16,
                               wmma::row_major> vf[2];
                wmma::load_matrix_sync(pf, &Ph[r0 * FB_LDB + kk * 16], FB_LDB);
#pragma unroll
                for (int j = 0; j < 2; j++)
                    wmma::load_matrix_sync(vf[j],
                                           &Vs[cur][(kk * 16) * FB_LDB + c0 + j * 16],
                                           FB_LDB);
#pragma unroll
                for (int j = 0; j < 2; j++)
                    wmma::mma_sync(oa[j], pf, vf[j], oa[j]);
            }
#pragma unroll
            for (int j = 0; j < 2; j++)
                wmma::store_matrix_sync(&Os[r0 * FB_LDF + c0 + j * 16], oa[j],
                                        FB_LDF, wmma::mem_row_major);
        }
        // barrier [A] of next iteration protects Ss/Ph/Os/KV reuse
    }
    __syncthreads();

    // Write att fp16: out[b, t0+row, h*64+c] = fp16(O/l).
    {
        const int row = tid >> 2;
        const int qgrp = tid & 3;
        const float invl = 1.0f / l_s[row];
        const size_t obase = ((size_t)(b * 2048 + t0 + row)) * 1024 + h * 64 + qgrp * 16;
        const float* orow = &Os[row * FB_LDF + qgrp * 16];
        f16 o8[8];
#pragma unroll
        for (int half = 0; half < 2; half++) {
#pragma unroll
            for (int u = 0; u < 8; u++)
                o8[u] = __float2half_rn(orow[half * 8 + u] * invl);
            *(uint4*)(out + obase + half * 8) = *(uint4*)o8;
        }
    }
}

// ---------------------------------------------------------------------------
// kernel_launch
// ---------------------------------------------------------------------------
extern "C" void kernel_launch(void* const* d_in, const int* in_sizes, int n_in,
                              void* d_out, int out_size) {
    const float* inputs = (const float*)d_in[0];
    const float* ln1_g  = (const float*)d_in[3];
    const float* ln1_b  = (const float*)d_in[4];
    const float* ln2_g  = (const float*)d_in[5];
    const float* ln2_b  = (const float*)d_in[6];
    const float* w_qkv  = (const float*)d_in[7];
    const float* w_out  = (const float*)d_in[8];
    const float* b_out  = (const float*)d_in[9];
    const float* w1     = (const float*)d_in[10];
    const float* b1     = (const float*)d_in[11];
    const float* w2     = (const float*)d_in[12];
    const float* b2     = (const float*)d_in[13];
    float* out = (float*)d_out;

    f16 *xn, *qkv, *att, *hn, *h, *wqkv_h, *wout_h, *w1_h, *w2_h;
    float *x;
    cudaGetSymbolAddress((void**)&xn,     g_xn);
    cudaGetSymbolAddress((void**)&qkv,    g_qkv);
    cudaGetSymbolAddress((void**)&att,    g_att);
    cudaGetSymbolAddress((void**)&x,      g_x);
    cudaGetSymbolAddress((void**)&hn,     g_hn);
    cudaGetSymbolAddress((void**)&h,      g_h);
    cudaGetSymbolAddress((void**)&wqkv_h, g_wqkv_h);
    cudaGetSymbolAddress((void**)&wout_h, g_wout_h);
    cudaGetSymbolAddress((void**)&w1_h,   g_w1_h);
    cudaGetSymbolAddress((void**)&w2_h,   g_w2_h);

    cudaFuncSetAttribute(gemm_hf<0>, cudaFuncAttributeMaxDynamicSharedMemorySize, G_SMEM);
    cudaFuncSetAttribute(gemm_hf<2>, cudaFuncAttributeMaxDynamicSharedMemorySize, G_SMEM);
    cudaFuncSetAttribute(gemm_hf<3>, cudaFuncAttributeMaxDynamicSharedMemorySize, G_SMEM);
    cudaFuncSetAttribute(flash_attn_hf, cudaFuncAttributeMaxDynamicSharedMemorySize, FB_SMEM);

    // 0. Convert weights to fp16
    cvt_f16_k<<<(D_DIM * D3)    / 1024, 256>>>(w_qkv, wqkv_h);
    cvt_f16_k<<<(D_DIM * D_DIM) / 1024, 256>>>(w_out, wout_h);
    cvt_f16_k<<<(D_DIM * MLP_D) / 1024, 256>>>(w1, w1_h);
    cvt_f16_k<<<(MLP_D * D_DIM) / 1024, 256>>>(w2, w2_h);

    // 1. x_n = fp16(LN1(inputs))
    ln_f16_k<<<M_ROWS, 256>>>(inputs, ln1_g, ln1_b, xn);

    // 2. qkv = fp16(x_n @ w_qkv)
    gemm_hf<0><<<dim3(D3 / 128, M_ROWS / 128), 256, G_SMEM>>>(
        xn, wqkv_h, nullptr, nullptr, qkv, M_ROWS, D3, D_DIM);

    // 3. attention -> att (fp16)
    flash_attn_hf<<<dim3(32, 16, 2), 256, FB_SMEM>>>(qkv, att);

    // 4. x = att @ w_out + b_out + inputs   (fp32)
    gemm_hf<2><<<dim3(D_DIM / 128, M_ROWS / 128), 256, G_SMEM>>>(
        att, wout_h, b_out, inputs, x, M_ROWS, D_DIM, D_DIM);

    // 5. h_n = fp16(LN2(x))
    ln_f16_k<<<M_ROWS, 256>>>(x, ln2_g, ln2_b, hn);

    // 6. h = fp16(gelu(h_n @ w1 + b1))
    gemm_hf<3><<<dim3(MLP_D / 128, M_ROWS / 128), 256, G_SMEM>>>(
        hn, w1_h, b1, nullptr, h, M_ROWS, MLP_D, D_DIM);

    // 7. out = h @ w2 + b2 + x   (fp32)
    gemm_hf<2><<<dim3(D_DIM / 128, M_ROWS / 128), 256, G_SMEM>>>(
        h, w2_h, b2, x, out, M_ROWS, D_DIM, MLP_D);
}

// round 17
// speedup vs baseline: 3.3857x; 1.4727x over previous
#include <cuda_runtime.h>
#include <cuda_fp16.h>
#include <math.h>
#include <stdint.h>
#include <mma.h>

using namespace nvcuda;
typedef __half f16;

// ---------------------------------------------------------------------------
// Problem constants: B=2, T=2048, D=1024, NH=16, DH=64, MLP=4096. M = 4096.
// ---------------------------------------------------------------------------
#define M_ROWS 4096
#define D_DIM  1024
#define D3     3072
#define MLP_D  4096

// Scratch (device globals; no allocation allowed)
__device__ f16   g_xn  [M_ROWS * D_DIM];
__device__ f16   g_qkv [M_ROWS * D3];
__device__ f16   g_att [M_ROWS * D_DIM];
__device__ float g_x   [M_ROWS * D_DIM];
__device__ f16   g_hn  [M_ROWS * D_DIM];
__device__ f16   g_h   [M_ROWS * MLP_D];
// fp16 weights
__device__ f16 g_wqkv_h[D_DIM * D3];
__device__ f16 g_wout_h[D_DIM * D_DIM];
__device__ f16 g_w1_h  [D_DIM * MLP_D];
__device__ f16 g_w2_h  [MLP_D * D_DIM];

// ---------------------------------------------------------------------------
// PTX helpers
// ---------------------------------------------------------------------------
__device__ __forceinline__ void cp16(uint32_t dst, const void* src) {
    asm volatile("cp.async.cg.shared.global [%0], [%1], 16;" :: "r"(dst), "l"(src));
}
#define CP_COMMIT() asm volatile("cp.async.commit_group;" ::: "memory")
template <int N>
__device__ __forceinline__ void cp_wait() {
    asm volatile("cp.async.wait_group %0;" :: "n"(N) : "memory");
}
__device__ __forceinline__ uint32_t sm_u32(const void* p) {
    return (uint32_t)__cvta_generic_to_shared(p);
}
__device__ __forceinline__ void ldsm4(uint32_t* r, uint32_t a) {
    asm volatile("ldmatrix.sync.aligned.m8n8.x4.shared.b16 {%0,%1,%2,%3}, [%4];"
                 : "=r"(r[0]), "=r"(r[1]), "=r"(r[2]), "=r"(r[3]) : "r"(a));
}
__device__ __forceinline__ void ldsm4t(uint32_t* r, uint32_t a) {
    asm volatile("ldmatrix.sync.aligned.m8n8.x4.trans.shared.b16 {%0,%1,%2,%3}, [%4];"
                 : "=r"(r[0]), "=r"(r[1]), "=r"(r[2]), "=r"(r[3]) : "r"(a));
}
__device__ __forceinline__ void mma16816(float* c, const uint32_t* a,
                                         uint32_t b0, uint32_t b1) {
    asm volatile(
        "mma.sync.aligned.m16n8k16.row.col.f32.f16.f16.f32 "
        "{%0,%1,%2,%3}, {%4,%5,%6,%7}, {%8,%9}, {%0,%1,%2,%3};"
        : "+f"(c[0]), "+f"(c[1]), "+f"(c[2]), "+f"(c[3])
        : "r"(a[0]), "r"(a[1]), "r"(a[2]), "r"(a[3]), "r"(b0), "r"(b1));
}
__device__ __forceinline__ uint32_t pack_h2(float x, float y) {
    __half2 h = __floats2half2_rn(x, y);
    return *reinterpret_cast<uint32_t*>(&h);
}

// ---------------------------------------------------------------------------
// All-weights fp32 -> fp16 conversion in one launch.
// ---------------------------------------------------------------------------
#define CVT_N0 3145728            // qkv
#define CVT_N1 4194304            // + wout
#define CVT_N2 8388608            // + w1
#define CVT_N3 12582912           // + w2

__global__ void cvt_all_k(const float* __restrict__ s0, const float* __restrict__ s1,
                          const float* __restrict__ s2, const float* __restrict__ s3,
                          f16* __restrict__ d0, f16* __restrict__ d1,
                          f16* __restrict__ d2, f16* __restrict__ d3) {
    const int i = (blockIdx.x * 256 + threadIdx.x) * 4;
    const float* src;
    f16* dst;
    int off;
    if (i < CVT_N0)      { src = s0; dst = d0; off = i; }
    else if (i < CVT_N1) { src = s1; dst = d1; off = i - CVT_N0; }
    else if (i < CVT_N2) { src = s2; dst = d2; off = i - CVT_N1; }
    else                 { src = s3; dst = d3; off = i - CVT_N2; }
    const float4 v = *(const float4*)(src + off);
    f16 o[4] = {__float2half_rn(v.x), __float2half_rn(v.y),
                __float2half_rn(v.z), __float2half_rn(v.w)};
    *(uint64_t*)(dst + off) = *(uint64_t*)o;
}

// ---------------------------------------------------------------------------
// LayerNorm: one block (256 threads) per row of 1024 floats -> fp16 out.
// ---------------------------------------------------------------------------
__global__ void ln_f16_k(const float* __restrict__ x, const float* __restrict__ g,
                         const float* __restrict__ b, f16* __restrict__ y) {
    __shared__ float rs[8], rss[8], sh[2];
    const int row = blockIdx.x;
    const int tid = threadIdx.x;
    const float4 v = *(const float4*)(x + (size_t)row * 1024 + tid * 4);
    float s  = v.x + v.y + v.z + v.w;
    float ss = v.x * v.x + v.y * v.y + v.z * v.z + v.w * v.w;
#pragma unroll
    for (int off = 16; off >= 1; off >>= 1) {
        s  += __shfl_xor_sync(0xffffffffu, s, off);
        ss += __shfl_xor_sync(0xffffffffu, ss, off);
    }
    if ((tid & 31) == 0) { rs[tid >> 5] = s; rss[tid >> 5] = ss; }
    __syncthreads();
    if (tid == 0) {
        float S = 0.f, SS = 0.f;
#pragma unroll
        for (int w = 0; w < 8; w++) { S += rs[w]; SS += rss[w]; }
        sh[0] = S * (1.0f / 1024.0f);
        sh[1] = SS * (1.0f / 1024.0f);
    }
    __syncthreads();
    const float mu   = sh[0];
    const float var  = sh[1] - mu * mu;
    const float rstd = rsqrtf(var + 1e-5f);
    const float4 gg = *(const float4*)(g + tid * 4);
    const float4 bb = *(const float4*)(b + tid * 4);
    f16 o[4];
    o[0] = __float2half_rn((v.x - mu) * rstd * gg.x + bb.x);
    o[1] = __float2half_rn((v.y - mu) * rstd * gg.y + bb.y);
    o[2] = __float2half_rn((v.z - mu) * rstd * gg.z + bb.z);
    o[3] = __float2half_rn((v.w - mu) * rstd * gg.w + bb.w);
    *(uint64_t*)(y + (size_t)row * 1024 + tid * 4) = *(uint64_t*)o;
}

// ---------------------------------------------------------------------------
// WMMA fp16 GEMM (fp32 accum), 2-stage cp.async, BK=64, 1 barrier / K-iter.
//   EPI 0: C fp16   2: C fp32 = +bias+res   3: C fp16 = gelu(.+bias)
// CTA tile 128x128, 256 threads, 8 warps, warp tile 32x64.
// ---------------------------------------------------------------------------
#define GB_AS_LD 72
#define GB_BS_LD 136
#define GB_STG (128 * GB_AS_LD + 64 * GB_BS_LD)   // 17920 f16 / stage
#define G_EP_LD 68
#define G_SMEM (2 * GB_STG * 2)                   // 71680 B (epi 69632 fits)

__device__ __forceinline__ void g_load_stage(
    const f16* __restrict__ A, const f16* __restrict__ B,
    int N, int K, int m0, int n0, int k0, f16* As, f16* Bs, int tid) {
#pragma unroll
    for (int v = 0; v < 4; v++) {
        const int id = v * 256 + tid;
        const int r  = id >> 3;          // 0..127
        const int s  = (id & 7) * 8;     // 0..56
        cp16(sm_u32(&As[r * GB_AS_LD + s]), A + (size_t)(m0 + r) * K + k0 + s);
    }
#pragma unroll
    for (int v = 0; v < 4; v++) {
        const int id = v * 256 + tid;
        const int r  = id >> 4;          // 0..63
        const int s  = (id & 15) * 8;    // 0..120
        cp16(sm_u32(&Bs[r * GB_BS_LD + s]), B + (size_t)(k0 + r) * N + n0 + s);
    }
}

template <int EPI>
__global__ __launch_bounds__(256, 2)
void gemm_hf(const f16* __restrict__ A, const f16* __restrict__ B,
             const float* __restrict__ bias, const float* __restrict__ res,
             void* __restrict__ Cv, int M, int N, int K) {
    extern __shared__ char smc[];
    f16* As[2] = {(f16*)smc, (f16*)smc + GB_STG};
    f16* Bs[2] = {(f16*)smc + 128 * GB_AS_LD, (f16*)smc + GB_STG + 128 * GB_AS_LD};

    const int tid  = threadIdx.x;
    const int wid  = tid >> 5;
    const int lane = tid & 31;
    const int m0 = blockIdx.y * 128;
    const int n0 = blockIdx.x * 128;
    const int wm = (wid & 3) * 32;
    const int wn = (wid >> 2) * 64;

    wmma::fragment<wmma::accumulator, 16, 16, 16, float> acc[2][4];
#pragma unroll
    for (int i = 0; i < 2; i++)
#pragma unroll
        for (int j = 0; j < 4; j++)
            wmma::fill_fragment(acc[i][j], 0.0f);

    const int NK = K / 64;
    g_load_stage(A, B, N, K, m0, n0, 0, As[0], Bs[0], tid);
    CP_COMMIT();

    for (int kt = 0; kt < NK; kt++) {
        cp_wait<0>();
        __syncthreads();   // stage kt visible; slot kt^1 readers retired

        if (kt + 1 < NK) {
            g_load_stage(A, B, N, K, m0, n0, (kt + 1) * 64,
                         As[(kt + 1) & 1], Bs[(kt + 1) & 1], tid);
            CP_COMMIT();
        }

        const f16* as = As[kt & 1];
        const f16* bs = Bs[kt & 1];
#pragma unroll
        for (int kk = 0; kk < 4; kk++) {
            wmma::fragment<wmma::matrix_a, 16, 16, 16, f16, wmma::row_major> af[2];
            wmma::fragment<wmma::matrix_b, 16, 16, 16, f16, wmma::row_major> bf_[4];
#pragma unroll
            for (int i = 0; i < 2; i++)
                wmma::load_matrix_sync(af[i], &as[(wm + i * 16) * GB_AS_LD + kk * 16],
                                       GB_AS_LD);
#pragma unroll
            for (int j = 0; j < 4; j++)
                wmma::load_matrix_sync(bf_[j], &bs[(kk * 16) * GB_BS_LD + wn + j * 16],
                                       GB_BS_LD);
#pragma unroll
            for (int i = 0; i < 2; i++)
#pragma unroll
                for (int j = 0; j < 4; j++)
                    wmma::mma_sync(acc[i][j], af[i], bf_[j], acc[i][j]);
        }
    }
    __syncthreads();   // protect stage smem before epilogue reuse

    float* ep = (float*)smc + wid * (32 * G_EP_LD);
#pragma unroll
    for (int i = 0; i < 2; i++)
#pragma unroll
        for (int j = 0; j < 4; j++)
            wmma::store_matrix_sync(&ep[(i * 16) * G_EP_LD + j * 16], acc[i][j],
                                    G_EP_LD, wmma::mem_row_major);
    __syncwarp();

#pragma unroll 4
    for (int r = 0; r < 32; r++) {
        const int m = m0 + wm + r;
#pragma unroll
        for (int cc = 0; cc < 2; cc++) {
            const int c = lane + cc * 32;
            const int n = n0 + wn + c;
            float v = ep[r * G_EP_LD + c];
            if (EPI == 2 || EPI == 3) v += bias[n];
            if (EPI == 2) v += res[(size_t)m * N + n];
            if (EPI == 3) v = 0.5f * v * (1.0f + erff(v * 0.7071067811865476f));
            if (EPI == 2) ((float*)Cv)[(size_t)m * N + n] = v;
            else          ((f16*)Cv)[(size_t)m * N + n] = __float2half_rn(v);
        }
    }
}

// ---------------------------------------------------------------------------
// FA2-style flash attention on raw mma.m16n8k16 PTX.
// CTA: 256 threads (8 warps), 128 q-rows x one head x one batch.
// Warp w owns S rows 16w..16w+15 ENTIRELY -> softmax warp-local, O in regs.
// Only barrier: KV double-buffer swap (1 per k-tile).
// Smem: Q stage 128x72 f16 (reused for output), K/V double buffers 64x72.
// ---------------------------------------------------------------------------
#define FA_LD  72
#define FA_KV  18432                       // after Q stage (128*72*2)
#define FA_SMEM (18432 + 4 * 9216)         // 55296 B

__device__ __forceinline__ void fa_load_kv(const f16* __restrict__ kvbase, int kt,
                                           f16* K, f16* V, int tid) {
    const f16* kb = kvbase + (size_t)(kt * 64) * 3072;
#pragma unroll
    for (int v = 0; v < 2; v++) {
        const int id = v * 256 + tid;
        const int r  = id >> 3;         // 0..63
        const int s  = (id & 7) * 8;
        cp16(sm_u32(&K[r * FA_LD + s]), kb + (size_t)r * 3072 + s);
        cp16(sm_u32(&V[r * FA_LD + s]), kb + 1024 + (size_t)r * 3072 + s);
    }
}

__global__ __launch_bounds__(256, 2)
void flash_attn_mma(const f16* __restrict__ qkv, f16* __restrict__ out) {
    extern __shared__ char smc[];
    f16* Qs = (f16*)smc;
    f16* Kb[2] = {(f16*)(smc + FA_KV), (f16*)(smc + FA_KV + 18432)};
    f16* Vb[2] = {(f16*)(smc + FA_KV + 9216), (f16*)(smc + FA_KV + 27648)};

    const int qt = blockIdx.x;
    const int h  = blockIdx.y;
    const int b  = blockIdx.z;
    const int tid  = threadIdx.x;
    const int wid  = tid >> 5;
    const int lane = tid & 31;
    const int t0 = qt * 128;
    const int r0 = wid * 16;

    // ldmatrix lane address components (same pattern for A, B-notrans, B-trans)
    const int lrow = ((lane >> 3) & 1) * 8 + (lane & 7);
    const int lcol = (lane >> 4) * 8;

    const f16* kvbase = qkv + (size_t)(b * 2048) * 3072 + 1024 + h * 64;

    // Prefetch K/V tile 0
    fa_load_kv(kvbase, 0, Kb[0], Vb[0], tid);
    CP_COMMIT();

    // Stage Q (raw; 1/8 scale folded into S later)
    const f16* qbase = qkv + (size_t)(b * 2048 + t0) * 3072 + h * 64;
#pragma unroll
    for (int v = 0; v < 4; v++) {
        const int id = v * 256 + tid;
        const int r  = id >> 3;          // 0..127
        const int s  = (id & 7) * 8;
        *(uint4*)&Qs[r * FA_LD + s] = *(const uint4*)(qbase + (size_t)r * 3072 + s);
    }
    __syncthreads();

    // Extract Q A-fragments (16 rows x 64 dh = 4 k-tiles)
    uint32_t Qa[4][4];
#pragma unroll
    for (int kk = 0; kk < 4; kk++)
        ldsm4(Qa[kk], sm_u32(&Qs[(r0 + lrow) * FA_LD + kk * 16 + lcol]));

    // O accumulators: 8 dh-tiles x 4 regs; softmax state (rows lane/4, lane/4+8)
    float O[8][4];
#pragma unroll
    for (int j = 0; j < 8; j++) { O[j][0] = O[j][1] = O[j][2] = O[j][3] = 0.f; }
    float m0 = -INFINITY, m1 = -INFINITY, l0 = 0.f, l1 = 0.f;

    for (int kt = 0; kt < 32; kt++) {
        const int cur = kt & 1;
        cp_wait<0>();
        __syncthreads();     // [A] KV(kt) visible; all reads of KV(kt-1) retired

        if (kt + 1 < 32) {
            fa_load_kv(kvbase, kt + 1, Kb[cur ^ 1], Vb[cur ^ 1], tid);
            CP_COMMIT();
        }
        const f16* Kc = Kb[cur];
        const f16* Vc = Vb[cur];

        // S = Q @ K^T : 16 rows x 64 keys (8 n-tiles)
        float SC[8][4];
#pragma unroll
        for (int j = 0; j < 8; j++) { SC[j][0] = SC[j][1] = SC[j][2] = SC[j][3] = 0.f; }
#pragma unroll
        for (int jj = 0; jj < 4; jj++) {
#pragma unroll
            for (int kk = 0; kk < 4; kk++) {
                uint32_t kb4[4];
                ldsm4(kb4, sm_u32(&Kc[(16 * jj + lrow) * FA_LD + 16 * kk + lcol]));
                mma16816(SC[2 * jj],     Qa[kk], kb4[0], kb4[2]);
                mma16816(SC[2 * jj + 1], Qa[kk], kb4[1], kb4[3]);
            }
        }

        // Softmax (warp-local; quad shfl over lanes sharing a row)
        float mx0 = -INFINITY, mx1 = -INFINITY;
#pragma unroll
        for (int j = 0; j < 8; j++) {
            SC[j][0] *= 0.125f; SC[j][1] *= 0.125f;
            SC[j][2] *= 0.125f; SC[j][3] *= 0.125f;
            mx0 = fmaxf(mx0, fmaxf(SC[j][0], SC[j][1]));
            mx1 = fmaxf(mx1, fmaxf(SC[j][2], SC[j][3]));
        }
        mx0 = fmaxf(mx0, __shfl_xor_sync(0xffffffffu, mx0, 1));
        mx0 = fmaxf(mx0, __shfl_xor_sync(0xffffffffu, mx0, 2));
        mx1 = fmaxf(mx1, __shfl_xor_sync(0xffffffffu, mx1, 1));
        mx1 = fmaxf(mx1, __shfl_xor_sync(0xffffffffu, mx1, 2));
        const float mn0 = fmaxf(m0, mx0);
        const float mn1 = fmaxf(m1, mx1);
        const float a0 = __expf(m0 - mn0);
        const float a1 = __expf(m1 - mn1);
        m0 = mn0; m1 = mn1;
        float s0 = 0.f, s1 = 0.f;
#pragma unroll
        for (int j = 0; j < 8; j++) {
            SC[j][0] = __expf(SC[j][0] - m0); s0 += SC[j][0];
            SC[j][1] = __expf(SC[j][1] - m0); s0 += SC[j][1];
            SC[j][2] = __expf(SC[j][2] - m1); s1 += SC[j][2];
            SC[j][3] = __expf(SC[j][3] - m1); s1 += SC[j][3];
        }
        s0 += __shfl_xor_sync(0xffffffffu, s0, 1);
        s0 += __shfl_xor_sync(0xffffffffu, s0, 2);
        s1 += __shfl_xor_sync(0xffffffffu, s1, 1);
        s1 += __shfl_xor_sync(0xffffffffu, s1, 2);
        l0 = l0 * a0 + s0;
        l1 = l1 * a1 + s1;
#pragma unroll
        for (int j = 0; j < 8; j++) {
            O[j][0] *= a0; O[j][1] *= a0; O[j][2] *= a1; O[j][3] *= a1;
        }

        // P C-frags -> A-frags (in registers, no smem roundtrip)
        uint32_t Pa[4][4];
#pragma unroll
        for (int kk = 0; kk < 4; kk++) {
            Pa[kk][0] = pack_h2(SC[2 * kk][0],     SC[2 * kk][1]);
            Pa[kk][1] = pack_h2(SC[2 * kk][2],     SC[2 * kk][3]);
            Pa[kk][2] = pack_h2(SC[2 * kk + 1][0], SC[2 * kk + 1][1]);
            Pa[kk][3] = pack_h2(SC[2 * kk + 1][2], SC[2 * kk + 1][3]);
        }

        // O += P @ V
#pragma unroll
        for (int jj = 0; jj < 4; jj++) {
#pragma unroll
            for (int kk = 0; kk < 4; kk++) {
                uint32_t vb4[4];
                ldsm4t(vb4, sm_u32(&Vc[(16 * kk + lrow) * FA_LD + 16 * jj + lcol]));
                mma16816(O[2 * jj],     Pa[kk], vb4[0], vb4[1]);
                mma16816(O[2 * jj + 1], Pa[kk], vb4[2], vb4[3]);
            }
        }
    }

    // Normalize, stage to smem (reuse Qs), write coalesced.
    const float il0 = 1.0f / l0;
    const float il1 = 1.0f / l1;
    const int orow = r0 + (lane >> 2);
    const int ocol = 2 * (lane & 3);
#pragma unroll
    for (int j = 0; j < 8; j++) {
        *(uint32_t*)&Qs[orow * FA_LD + 8 * j + ocol] =
            pack_h2(O[j][0] * il0, O[j][1] * il0);
        *(uint32_t*)&Qs[(orow + 8) * FA_LD + 8 * j + ocol] =
            pack_h2(O[j][2] * il1, O[j][3] * il1);
    }
    __syncthreads();
#pragma unroll
    for (int v = 0; v < 4; v++) {
        const int id = v * 256 + tid;
        const int r  = id >> 3;
        const int s  = (id & 7) * 8;
        *(uint4*)(out + (size_t)(b * 2048 + t0 + r) * 1024 + h * 64 + s) =
            *(const uint4*)&Qs[r * FA_LD + s];
    }
}

// ---------------------------------------------------------------------------
// kernel_launch
// ---------------------------------------------------------------------------
extern "C" void kernel_launch(void* const* d_in, const int* in_sizes, int n_in,
                              void* d_out, int out_size) {
    const float* inputs = (const float*)d_in[0];
    const float* ln1_g  = (const float*)d_in[3];
    const float* ln1_b  = (const float*)d_in[4];
    const float* ln2_g  = (const float*)d_in[5];
    const float* ln2_b  = (const float*)d_in[6];
    const float* w_qkv  = (const float*)d_in[7];
    const float* w_out  = (const float*)d_in[8];
    const float* b_out  = (const float*)d_in[9];
    const float* w1     = (const float*)d_in[10];
    const float* b1     = (const float*)d_in[11];
    const float* w2     = (const float*)d_in[12];
    const float* b2     = (const float*)d_in[13];
    float* out = (float*)d_out;

    f16 *xn, *qkv, *att, *hn, *h, *wqkv_h, *wout_h, *w1_h, *w2_h;
    float *x;
    cudaGetSymbolAddress((void**)&xn,     g_xn);
    cudaGetSymbolAddress((void**)&qkv,    g_qkv);
    cudaGetSymbolAddress((void**)&att,    g_att);
    cudaGetSymbolAddress((void**)&x,      g_x);
    cudaGetSymbolAddress((void**)&hn,     g_hn);
    cudaGetSymbolAddress((void**)&h,      g_h);
    cudaGetSymbolAddress((void**)&wqkv_h, g_wqkv_h);
    cudaGetSymbolAddress((void**)&wout_h, g_wout_h);
    cudaGetSymbolAddress((void**)&w1_h,   g_w1_h);
    cudaGetSymbolAddress((void**)&w2_h,   g_w2_h);

    cudaFuncSetAttribute(gemm_hf<0>, cudaFuncAttributeMaxDynamicSharedMemorySize, G_SMEM);
    cudaFuncSetAttribute(gemm_hf<2>, cudaFuncAttributeMaxDynamicSharedMemorySize, G_SMEM);
    cudaFuncSetAttribute(gemm_hf<3>, cudaFuncAttributeMaxDynamicSharedMemorySize, G_SMEM);
    cudaFuncSetAttribute(flash_attn_mma, cudaFuncAttributeMaxDynamicSharedMemorySize, FA_SMEM);

    // 0. Convert all weights to fp16 (single launch)
    cvt_all_k<<<CVT_N3 / 1024, 256>>>(w_qkv, w_out, w1, w2,
                                      wqkv_h, wout_h, w1_h, w2_h);

    // 1. x_n = fp16(LN1(inputs))
    ln_f16_k<<<M_ROWS, 256>>>(inputs, ln1_g, ln1_b, xn);

    // 2. qkv = fp16(x_n @ w_qkv)
    gemm_hf<0><<<dim3(D3 / 128, M_ROWS / 128), 256, G_SMEM>>>(
        xn, wqkv_h, nullptr, nullptr, qkv, M_ROWS, D3, D_DIM);

    // 3. attention -> att (fp16)
    flash_attn_mma<<<dim3(16, 16, 2), 256, FA_SMEM>>>(qkv, att);

    // 4. x = att @ w_out + b_out + inputs   (fp32)
    gemm_hf<2><<<dim3(D_DIM / 128, M_ROWS / 128), 256, G_SMEM>>>(
        att, wout_h, b_out, inputs, x, M_ROWS, D_DIM, D_DIM);

    // 5. h_n = fp16(LN2(x))
    ln_f16_k<<<M_ROWS, 256>>>(x, ln2_g, ln2_b, hn);

    // 6. h = fp16(gelu(h_n @ w1 + b1))
    gemm_hf<3><<<dim3(MLP_D / 128, M_ROWS / 128), 256, G_SMEM>>>(
        hn, w1_h, b1, nullptr, h, M_ROWS, MLP_D, D_DIM);

    // 7. out = h @ w2 + b2 + x   (fp32)
    gemm_hf<2><<<dim3(D_DIM / 128, M_ROWS / 128), 256, G_SMEM>>>(
        h, w2_h, b2, x, out, M_ROWS, D_DIM, MLP_D);
}